// round 1
// baseline (speedup 1.0000x reference)
#include <cuda_runtime.h>
#include <math.h>

#define IMG   512
#define NANG  180
#define NBAT  4

// ---------------- scratch (no allocations allowed) ----------------
__device__ float  g_h[IMG];                 // spatial filter kernel (circular)
__device__ float2 g_trig[NANG];             // (sin, cos) per angle
__device__ float4 g_filt[NANG * IMG];       // filtered sinogram, batch-interleaved: [angle][p].{b0..b3}

// ---------------- setup: build shepp-logan spatial kernel + trig table ----------------
// One block, 512 threads. Two table-based 512-point DFTs (f -> ff -> h).
__global__ void setup_kernel() {
    __shared__ float s_cos[IMG];   // cos(2*pi*t/512)
    __shared__ float s_f[IMG];
    __shared__ float s_ff[IMG];
    const int t = threadIdx.x;

    // cos table: cos(pi * t/256) == cos(2*pi*t/512); t/256 exact in fp32
    s_cos[t] = cospif((float)t * (1.0f / 256.0f));

    // f: f[0]=0.25, f[j] = -1/(pi*m)^2 for odd j with m = min(j, 512-j)
    float fv = 0.0f;
    if (t == 0) fv = 0.25f;
    else if (t & 1) {
        int m = (t <= 255) ? t : (IMG - t);
        double pm = M_PI * (double)m;
        fv = (float)(-1.0 / (pm * pm));
    }
    s_f[t] = fv;

    // angle table: linspace(0,180,180) deg -> a * pi/179 rad
    if (t < NANG) {
        double th = (double)t * (M_PI / 179.0);
        g_trig[t] = make_float2((float)sin(th), (float)cos(th));
    }
    __syncthreads();

    // ff[k] = 2 * sum_j f[j] cos(2*pi*j*k/512)   (f real-even -> fft real)
    // only j==0 and odd j are nonzero
    float acc = (t == 0 || true) ? s_f[0] : 0.0f;   // j=0 term: cos(0)=1
    acc = s_f[0];
    #pragma unroll 4
    for (int j = 1; j < IMG; j += 2)
        acc = fmaf(s_f[j], s_cos[(j * t) & (IMG - 1)], acc);
    float ffk = 2.0f * acc;
    if (t > 0) {
        int m = (t <= 256) ? t : (IMG - t);          // |fftfreq| * N
        float x = (float)m * (1.0f / (float)IMG);    // exact
        float w = (float)M_PI * x;                   // omega
        ffk *= sinpif(x) / w;                        // sin(omega)/omega (even in omega)
    }
    s_ff[t] = ffk;
    __syncthreads();

    // h[q] = (1/512) * sum_k ff[k] cos(2*pi*k*q/512)
    float hacc = 0.0f;
    #pragma unroll 4
    for (int k = 0; k < IMG; ++k)
        hacc = fmaf(s_ff[k], s_cos[(k * t) & (IMG - 1)], hacc);
    g_h[t] = hacc * (1.0f / (float)IMG);
}

// ---------------- filtering: circular conv per (batch, angle) row ----------------
// grid (NANG, NBAT), block 512. Output batch-interleaved float4 rows.
__global__ void filter_kernel(const float* __restrict__ sino) {
    __shared__ float s_row[IMG];
    __shared__ float s_h[IMG];
    const int a = blockIdx.x;
    const int b = blockIdx.y;
    const int t = threadIdx.x;

    s_row[t] = sino[(b * NANG + a) * IMG + t];
    s_h[t]   = g_h[t];
    __syncthreads();

    float acc = 0.0f;
    #pragma unroll 8
    for (int q = 0; q < IMG; ++q)
        acc = fmaf(s_row[q], s_h[(t - q) & (IMG - 1)], acc);

    reinterpret_cast<float*>(g_filt)[(a * IMG + t) * 4 + b] = acc;
}

// ---------------- backprojection: 32x8 pixel tile per block, all 4 batches ----------------
__global__ __launch_bounds__(256) void backproj_kernel(float* __restrict__ out) {
    __shared__ float4 s_row[IMG];     // one angle's filtered row, 4 batches interleaved
    __shared__ float2 s_trig[NANG];

    const int t  = threadIdx.x;
    const int tx = t & 31;
    const int ty = t >> 5;
    const int w  = blockIdx.x * 32 + tx;
    const int h  = blockIdx.y * 8 + ty;

    if (t < NANG) s_trig[t] = g_trig[t];

    const float xf = 255.0f - (float)w;     // reversed x axis, centered
    const float yf = (float)h - 256.0f;

    float a0 = 0.0f, a1 = 0.0f, a2 = 0.0f, a3 = 0.0f;

    for (int a = 0; a < NANG; ++a) {
        __syncthreads();
        s_row[t]       = g_filt[a * IMG + t];
        s_row[t + 256] = g_filt[a * IMG + t + 256];
        __syncthreads();

        const float2 sc = s_trig[a];                       // (sin, cos)
        const float p   = fmaf(xf, sc.x, fmaf(yf, sc.y, 256.0f));
        const float fi  = floorf(p);
        const float fr  = p - fi;
        const int   i0  = (int)fi;

        const float4 z  = make_float4(0.f, 0.f, 0.f, 0.f);
        const float4 v0 = ((unsigned)i0       < (unsigned)IMG) ? s_row[i0]     : z;
        const float4 v1 = ((unsigned)(i0 + 1) < (unsigned)IMG) ? s_row[i0 + 1] : z;

        a0 += fmaf(fr, v1.x - v0.x, v0.x);
        a1 += fmaf(fr, v1.y - v0.y, v0.y);
        a2 += fmaf(fr, v1.z - v0.z, v0.z);
        a3 += fmaf(fr, v1.w - v0.w, v0.w);
    }

    // circle mask + pi/(2A) scaling
    const bool inside = fmaf(xf, xf, yf * yf) <= 65536.0f;   // 256^2
    const float scale = inside ? (float)(M_PI / (2.0 * NANG)) : 0.0f;

    const int pix = h * IMG + w;
    out[0 * IMG * IMG + pix] = a0 * scale;
    out[1 * IMG * IMG + pix] = a1 * scale;
    out[2 * IMG * IMG + pix] = a2 * scale;
    out[3 * IMG * IMG + pix] = a3 * scale;
}

// ---------------- launcher ----------------
extern "C" void kernel_launch(void* const* d_in, const int* in_sizes, int n_in,
                              void* d_out, int out_size) {
    const float* sino = (const float*)d_in[0];
    float* out = (float*)d_out;

    setup_kernel<<<1, 512>>>();
    filter_kernel<<<dim3(NANG, NBAT), 512>>>(sino);
    backproj_kernel<<<dim3(IMG / 32, IMG / 8), 256>>>(out);
}

// round 2
// speedup vs baseline: 1.2949x; 1.2949x over previous
#include <cuda_runtime.h>
#include <math.h>

#define IMG   512
#define NANG  180
#define NBAT  4

// ---------------- scratch (no allocations allowed) ----------------
__device__ float  g_ff[IMG];                // frequency-domain filter
__device__ float  g_h[IMG];                 // spatial filter kernel (circular)
__device__ float2 g_trig[NANG];             // (sin, cos) per angle
__device__ float4 g_filt[NANG * IMG];       // filtered sinogram, batch-interleaved

// ---------------- setup stage 1: ff[k] = 2*Re(fft(f))[k] * sinc window ----------------
// f[0]=0.25, f[j] = -1/(pi*m)^2 for odd j, m = min(j, 512-j). f real-even -> fft real.
__global__ void setup_ff() {                // grid 16, block 32
    const int k = blockIdx.x * 32 + threadIdx.x;
    float acc = 0.25f;                      // j = 0 term
    for (int j = 1; j < IMG; j += 2) {
        int m = (j <= 255) ? j : (IMG - j);
        float pm = (float)M_PI * (float)m;
        float fj = -1.0f / (pm * pm);
        int idx = (j * k) & (IMG - 1);
        acc = fmaf(fj, cospif((float)idx * (1.0f / 256.0f)), acc);
    }
    float ffk = 2.0f * acc;
    if (k > 0) {
        int m = (k <= 256) ? k : (IMG - k);          // |fftfreq|*N
        float x = (float)m * (1.0f / (float)IMG);    // exact
        ffk *= sinpif(x) / ((float)M_PI * x);        // sin(omega)/omega, even
    }
    g_ff[k] = ffk;
}

// ---------------- setup stage 2: h = ifft(ff) (real, via cosine DFT) + trig table ----------------
__global__ void setup_h() {                 // grid 16, block 32
    const int q = blockIdx.x * 32 + threadIdx.x;
    float acc = 0.0f;
    for (int k = 0; k < IMG; ++k) {
        int idx = (k * q) & (IMG - 1);
        acc = fmaf(g_ff[k], cospif((float)idx * (1.0f / 256.0f)), acc);
    }
    g_h[q] = acc * (1.0f / (float)IMG);
    if (q < NANG) {
        double th = (double)q * (M_PI / 179.0);      // linspace(0,180,180) deg -> rad
        g_trig[q] = make_float2((float)sin(th), (float)cos(th));
    }
}

// ---------------- filtering: circular conv, reversed-kernel float4 sliding window ----------------
// grid (NANG, NBAT), block 128. Each thread computes 4 outputs s = 4t..4t+3:
//   acc[s] = sum_u row[(u+s)&511] * hr[u],  hr[u] = h[(-u)&511]
__global__ void filter_kernel(const float* __restrict__ sino) {
    __shared__ float s_row[2 * IMG];   // row duplicated -> no modulo
    __shared__ float s_hr[IMG];
    const int a = blockIdx.x;
    const int b = blockIdx.y;
    const int t = threadIdx.x;         // 0..127

    float4 r4 = reinterpret_cast<const float4*>(sino + (b * NANG + a) * IMG)[t];
    reinterpret_cast<float4*>(s_row)[t]       = r4;
    reinterpret_cast<float4*>(s_row)[t + 128] = r4;

    float4 h4 = reinterpret_cast<const float4*>(g_h)[t];   // h[4t..4t+3]
    s_hr[(IMG - (4 * t + 0)) & (IMG - 1)] = h4.x;
    s_hr[(IMG - (4 * t + 1)) & (IMG - 1)] = h4.y;
    s_hr[(IMG - (4 * t + 2)) & (IMG - 1)] = h4.z;
    s_hr[(IMG - (4 * t + 3)) & (IMG - 1)] = h4.w;
    __syncthreads();

    float acc0 = 0.f, acc1 = 0.f, acc2 = 0.f, acc3 = 0.f;
    const int base = 4 * t;
    float4 R0 = *reinterpret_cast<const float4*>(&s_row[base]);
    #pragma unroll 4
    for (int u = 0; u < IMG; u += 4) {
        float4 HR = *reinterpret_cast<const float4*>(&s_hr[u]);                 // broadcast
        float4 R1 = *reinterpret_cast<const float4*>(&s_row[base + u + 4]);     // sliding
        acc0 = fmaf(R0.x, HR.x, fmaf(R0.y, HR.y, fmaf(R0.z, HR.z, fmaf(R0.w, HR.w, acc0))));
        acc1 = fmaf(R0.y, HR.x, fmaf(R0.z, HR.y, fmaf(R0.w, HR.z, fmaf(R1.x, HR.w, acc1))));
        acc2 = fmaf(R0.z, HR.x, fmaf(R0.w, HR.y, fmaf(R1.x, HR.z, fmaf(R1.y, HR.w, acc2))));
        acc3 = fmaf(R0.w, HR.x, fmaf(R1.x, HR.y, fmaf(R1.y, HR.z, fmaf(R1.z, HR.w, acc3))));
        R0 = R1;
    }

    float* out = reinterpret_cast<float*>(g_filt);
    const int s = a * IMG + base;
    out[(s + 0) * 4 + b] = acc0;
    out[(s + 1) * 4 + b] = acc1;
    out[(s + 2) * 4 + b] = acc2;
    out[(s + 3) * 4 + b] = acc3;
}

// ---------------- backprojection: 64x32 pixel tile / block, 4 px/thread, all 4 batches ----------------
__global__ __launch_bounds__(512) void backproj_kernel(float* __restrict__ out) {
    __shared__ float4 s_row[2][IMG];   // double-buffered angle row (batch-interleaved)
    __shared__ float2 s_trig[NANG];

    const int t  = threadIdx.x;
    const int tx = t & 63;
    const int ty = t >> 6;             // 0..7
    const int w  = blockIdx.x * 64 + tx;
    const int y0 = blockIdx.y * 32 + ty;

    if (t < NANG) s_trig[t] = g_trig[t];

    const float xf = 255.0f - (float)w;
    float yf[4];
    #pragma unroll
    for (int k = 0; k < 4; ++k) yf[k] = (float)(y0 + 8 * k) - 256.0f;

    // block-level circle early-out (tile entirely outside radius 256)
    {
        float xhi = 255.0f - (float)(blockIdx.x * 64);
        float xlo = xhi - 63.0f;
        float ylo = (float)(blockIdx.y * 32) - 256.0f;
        float yhi = ylo + 31.0f;
        float mx = (xlo <= 0.0f && 0.0f <= xhi) ? 0.0f : fminf(fabsf(xlo), fabsf(xhi));
        float my = (ylo <= 0.0f && 0.0f <= yhi) ? 0.0f : fminf(fabsf(ylo), fabsf(yhi));
        if (fmaf(mx, mx, my * my) > 65536.0f) {
            #pragma unroll
            for (int k = 0; k < 4; ++k) {
                int pix = (y0 + 8 * k) * IMG + w;
                out[0 * IMG * IMG + pix] = 0.0f;
                out[1 * IMG * IMG + pix] = 0.0f;
                out[2 * IMG * IMG + pix] = 0.0f;
                out[3 * IMG * IMG + pix] = 0.0f;
            }
            return;
        }
    }

    s_row[0][t] = g_filt[t];           // angle 0
    __syncthreads();

    float acc[4][4];
    #pragma unroll
    for (int k = 0; k < 4; ++k)
        #pragma unroll
        for (int b = 0; b < 4; ++b) acc[k][b] = 0.0f;

    for (int a = 0; a < NANG; ++a) {
        float4 nxt;
        const bool have = (a + 1 < NANG);
        if (have) nxt = g_filt[(a + 1) * IMG + t];     // prefetch next row

        const float2 sc  = s_trig[a];                  // (sin, cos)
        const float pxs  = fmaf(xf, sc.x, 256.0f);
        const float4* row = s_row[a & 1];

        #pragma unroll
        for (int k = 0; k < 4; ++k) {
            const float p  = fmaf(yf[k], sc.y, pxs);
            const float fi = floorf(p);
            const float fr = p - fi;
            const int   i0 = (int)fi;

            const float4 z  = make_float4(0.f, 0.f, 0.f, 0.f);
            const float4 v0 = ((unsigned)i0       < (unsigned)IMG) ? row[i0]     : z;
            const float4 v1 = ((unsigned)(i0 + 1) < (unsigned)IMG) ? row[i0 + 1] : z;
            const float om  = 1.0f - fr;

            acc[k][0] = fmaf(om, v0.x, fmaf(fr, v1.x, acc[k][0]));
            acc[k][1] = fmaf(om, v0.y, fmaf(fr, v1.y, acc[k][1]));
            acc[k][2] = fmaf(om, v0.z, fmaf(fr, v1.z, acc[k][2]));
            acc[k][3] = fmaf(om, v0.w, fmaf(fr, v1.w, acc[k][3]));
        }

        if (have) s_row[(a + 1) & 1][t] = nxt;
        __syncthreads();               // single barrier per angle (double buffer)
    }

    const float gscale = (float)(M_PI / (2.0 * NANG));
    #pragma unroll
    for (int k = 0; k < 4; ++k) {
        const bool inside = fmaf(xf, xf, yf[k] * yf[k]) <= 65536.0f;
        const float g = inside ? gscale : 0.0f;
        const int pix = (y0 + 8 * k) * IMG + w;
        out[0 * IMG * IMG + pix] = acc[k][0] * g;
        out[1 * IMG * IMG + pix] = acc[k][1] * g;
        out[2 * IMG * IMG + pix] = acc[k][2] * g;
        out[3 * IMG * IMG + pix] = acc[k][3] * g;
    }
}

// ---------------- launcher ----------------
extern "C" void kernel_launch(void* const* d_in, const int* in_sizes, int n_in,
                              void* d_out, int out_size) {
    const float* sino = (const float*)d_in[0];
    float* out = (float*)d_out;

    setup_ff<<<16, 32>>>();
    setup_h<<<16, 32>>>();
    filter_kernel<<<dim3(NANG, NBAT), 128>>>(sino);
    backproj_kernel<<<dim3(IMG / 64, IMG / 32), 512>>>(out);
}

// round 4
// speedup vs baseline: 1.6041x; 1.2388x over previous
#include <cuda_runtime.h>
#include <math.h>

#define IMG   512
#define NANG  180
#define NBAT  4
#define CH    4          // angles staged per barrier pair (180 % 4 == 0)

// ---------------- scratch (no allocations allowed) ----------------
__device__ float  g_ff[IMG];                // frequency-domain filter
__device__ float  g_h[IMG];                 // spatial filter kernel (circular)
__device__ float2 g_trig[NANG];             // (sin, cos) per angle
__device__ float4 g_filt[NANG * IMG];       // filtered sinogram, batch-interleaved

// ---------------- setup stage 1: ff[k] = 2*Re(fft(f))[k] * sinc window ----------------
__global__ void setup_ff() {                // grid 16, block 32
    const int k = blockIdx.x * 32 + threadIdx.x;
    float acc = 0.25f;                      // j = 0 term
    for (int j = 1; j < IMG; j += 2) {
        int m = (j <= 255) ? j : (IMG - j);
        float pm = (float)M_PI * (float)m;
        float fj = -1.0f / (pm * pm);
        int idx = (j * k) & (IMG - 1);
        acc = fmaf(fj, cospif((float)idx * (1.0f / 256.0f)), acc);
    }
    float ffk = 2.0f * acc;
    if (k > 0) {
        int m = (k <= 256) ? k : (IMG - k);          // |fftfreq|*N
        float x = (float)m * (1.0f / (float)IMG);    // exact
        ffk *= sinpif(x) / ((float)M_PI * x);        // sin(omega)/omega, even
    }
    g_ff[k] = ffk;
}

// ---------------- setup stage 2: h = ifft(ff) (cosine DFT) + trig table ----------------
__global__ void setup_h() {                 // grid 16, block 32
    const int q = blockIdx.x * 32 + threadIdx.x;
    float acc = 0.0f;
    for (int k = 0; k < IMG; ++k) {
        int idx = (k * q) & (IMG - 1);
        acc = fmaf(g_ff[k], cospif((float)idx * (1.0f / 256.0f)), acc);
    }
    g_h[q] = acc * (1.0f / (float)IMG);
    if (q < NANG) {
        double th = (double)q * (M_PI / 179.0);      // linspace(0,180,180) deg -> rad
        g_trig[q] = make_float2((float)sin(th), (float)cos(th));
    }
}

// ---------------- filtering: circular conv, reversed-kernel float4 sliding window ----------------
__global__ void filter_kernel(const float* __restrict__ sino) {
    __shared__ float s_row[2 * IMG];   // row duplicated -> no modulo
    __shared__ float s_hr[IMG];
    const int a = blockIdx.x;
    const int b = blockIdx.y;
    const int t = threadIdx.x;         // 0..127

    float4 r4 = reinterpret_cast<const float4*>(sino + (b * NANG + a) * IMG)[t];
    reinterpret_cast<float4*>(s_row)[t]       = r4;
    reinterpret_cast<float4*>(s_row)[t + 128] = r4;

    float4 h4 = reinterpret_cast<const float4*>(g_h)[t];   // h[4t..4t+3]
    s_hr[(IMG - (4 * t + 0)) & (IMG - 1)] = h4.x;
    s_hr[(IMG - (4 * t + 1)) & (IMG - 1)] = h4.y;
    s_hr[(IMG - (4 * t + 2)) & (IMG - 1)] = h4.z;
    s_hr[(IMG - (4 * t + 3)) & (IMG - 1)] = h4.w;
    __syncthreads();

    float acc0 = 0.f, acc1 = 0.f, acc2 = 0.f, acc3 = 0.f;
    const int base = 4 * t;
    float4 R0 = *reinterpret_cast<const float4*>(&s_row[base]);
    #pragma unroll 4
    for (int u = 0; u < IMG; u += 4) {
        float4 HR = *reinterpret_cast<const float4*>(&s_hr[u]);                 // broadcast
        float4 R1 = *reinterpret_cast<const float4*>(&s_row[base + u + 4]);     // sliding
        acc0 = fmaf(R0.x, HR.x, fmaf(R0.y, HR.y, fmaf(R0.z, HR.z, fmaf(R0.w, HR.w, acc0))));
        acc1 = fmaf(R0.y, HR.x, fmaf(R0.z, HR.y, fmaf(R0.w, HR.z, fmaf(R1.x, HR.w, acc1))));
        acc2 = fmaf(R0.z, HR.x, fmaf(R0.w, HR.y, fmaf(R1.x, HR.z, fmaf(R1.y, HR.w, acc2))));
        acc3 = fmaf(R0.w, HR.x, fmaf(R1.x, HR.y, fmaf(R1.y, HR.z, fmaf(R1.z, HR.w, acc3))));
        R0 = R1;
    }

    float* out = reinterpret_cast<float*>(g_filt);
    const int s = a * IMG + base;
    out[(s + 0) * 4 + b] = acc0;
    out[(s + 1) * 4 + b] = acc1;
    out[(s + 2) * 4 + b] = acc2;
    out[(s + 3) * 4 + b] = acc3;
}

// ---------------- backprojection: 32x32 tile / block, 4 px/thread, clamp-pad taps ----------------
// Padded row layout: slot 0 = zero, slots 1..512 = row[0..511], slots 513..515 = zero.
// p clamped to [-1, 513] before floor -> taps always in-bounds, boundary weights exact:
//   p in (-1,0): om*pad0 + fr*row[0];  p in [511,512): om*row[511] + fr*pad;  p<=-1 or >=512+1: both pads.
__global__ __launch_bounds__(256) void backproj_kernel(float* __restrict__ out) {
    __shared__ float4 s_rows[CH][IMG + 4];
    __shared__ float2 s_trig[NANG];

    const int t  = threadIdx.x;
    const int tx = t & 31;
    const int ty = t >> 5;             // 0..7
    const int w  = blockIdx.x * 32 + tx;
    const int y0 = blockIdx.y * 32 + ty;

    if (t < NANG) s_trig[t] = g_trig[t];
    if (t < CH * 4) {                  // zero the pad slots once
        int c = t >> 2, s = t & 3;
        int slot = (s == 0) ? 0 : (IMG + s);   // 0, 513, 514, 515
        s_rows[c][slot] = make_float4(0.f, 0.f, 0.f, 0.f);
    }

    const float xf = 255.0f - (float)w;
    float yf[4];
    #pragma unroll
    for (int k = 0; k < 4; ++k) yf[k] = (float)(y0 + 8 * k) - 256.0f;

    // block-level circle early-out (tile entirely outside radius 256)
    {
        float xhi = 255.0f - (float)(blockIdx.x * 32);
        float xlo = xhi - 31.0f;
        float ylo = (float)(blockIdx.y * 32) - 256.0f;
        float yhi = ylo + 31.0f;
        float mx = (xlo <= 0.0f && 0.0f <= xhi) ? 0.0f : fminf(fabsf(xlo), fabsf(xhi));
        float my = (ylo <= 0.0f && 0.0f <= yhi) ? 0.0f : fminf(fabsf(ylo), fabsf(yhi));
        if (fmaf(mx, mx, my * my) > 65536.0f) {
            #pragma unroll
            for (int k = 0; k < 4; ++k) {
                int pix = (y0 + 8 * k) * IMG + w;
                out[0 * IMG * IMG + pix] = 0.0f;
                out[1 * IMG * IMG + pix] = 0.0f;
                out[2 * IMG * IMG + pix] = 0.0f;
                out[3 * IMG * IMG + pix] = 0.0f;
            }
            return;
        }
    }

    float acc[4][4];
    #pragma unroll
    for (int k = 0; k < 4; ++k)
        #pragma unroll
        for (int b = 0; b < 4; ++b) acc[k][b] = 0.0f;

    for (int c0 = 0; c0 < NANG; c0 += CH) {
        // stage CH rows: CH*512 float4 / 256 threads = CH*2 each
        #pragma unroll
        for (int i = 0; i < CH * 2; ++i) {
            int idx = i * 256 + t;                 // 0 .. CH*512-1
            int r   = idx >> 9;
            int p   = idx & (IMG - 1);
            s_rows[r][p + 1] = g_filt[(c0 + r) * IMG + p];
        }
        __syncthreads();

        #pragma unroll
        for (int ci = 0; ci < CH; ++ci) {
            const float2 sc   = s_trig[c0 + ci];        // (sin, cos)
            const float  pxs  = fmaf(xf, sc.x, 256.0f);
            const float4* row = s_rows[ci];

            #pragma unroll
            for (int k = 0; k < 4; ++k) {
                float p  = fmaf(yf[k], sc.y, pxs);
                p        = fminf(fmaxf(p, -1.0f), 513.0f);
                float fi = floorf(p);
                float fr = p - fi;
                float om = 1.0f - fr;
                int   i0 = (int)fi;

                const float4 v0 = row[i0 + 1];
                const float4 v1 = row[i0 + 2];

                acc[k][0] = fmaf(om, v0.x, fmaf(fr, v1.x, acc[k][0]));
                acc[k][1] = fmaf(om, v0.y, fmaf(fr, v1.y, acc[k][1]));
                acc[k][2] = fmaf(om, v0.z, fmaf(fr, v1.z, acc[k][2]));
                acc[k][3] = fmaf(om, v0.w, fmaf(fr, v1.w, acc[k][3]));
            }
        }
        __syncthreads();
    }

    const float gscale = (float)(M_PI / (2.0 * NANG));
    #pragma unroll
    for (int k = 0; k < 4; ++k) {
        const bool inside = fmaf(xf, xf, yf[k] * yf[k]) <= 65536.0f;
        const float g = inside ? gscale : 0.0f;
        const int pix = (y0 + 8 * k) * IMG + w;
        out[0 * IMG * IMG + pix] = acc[k][0] * g;
        out[1 * IMG * IMG + pix] = acc[k][1] * g;
        out[2 * IMG * IMG + pix] = acc[k][2] * g;
        out[3 * IMG * IMG + pix] = acc[k][3] * g;
    }
}

// ---------------- launcher ----------------
extern "C" void kernel_launch(void* const* d_in, const int* in_sizes, int n_in,
                              void* d_out, int out_size) {
    const float* sino = (const float*)d_in[0];
    float* out = (float*)d_out;

    setup_ff<<<16, 32>>>();
    setup_h<<<16, 32>>>();
    filter_kernel<<<dim3(NANG, NBAT), 128>>>(sino);
    backproj_kernel<<<dim3(IMG / 32, IMG / 32), 256>>>(out);
}